// round 8
// baseline (speedup 1.0000x reference)
#include <cuda_runtime.h>
#include <math.h>

#define BB 32
#define SS 2048
#define HH 1024
#define UU 128
#define H4 (HH / 4)        // 256 float4 per row
#define KC 8               // split-K for k_v
#define CH 32              // attn chunks per batch (one block each)
#define RPC (SS / CH)      // 64 rows per chunk
#define TILE 8             // rows per cp.async tile (32 KB)
#define NT (RPC / TILE)    // 8 tiles per block
#define DEPTH 3            // ring depth (96 KB dynamic smem)
#define JC2 64             // j-chunks for output GEMM
#define JCW (2 * HH / JC2) // 32 j-rows per chunk
#define BG 4               // batch groups for output GEMM (8 batches each)

// ---- device scratch (no runtime allocation allowed) ----
__device__ float g_vp[KC * BB * HH];                // split-K partials of v = W @ h_t
__device__ float g_pm[BB * CH];                     // per-chunk running max
__device__ float g_pl[BB * CH];                     // per-chunk denom
__device__ float g_pacc[(size_t)BB * CH * HH];      // per-chunk unnormalized context (4 MB)
__device__ float g_pre[BB * 2 * HH];                // [context ; h_t]
__device__ float g_pout[JC2 * BB * UU];             // split-K partials of final GEMM (1 MB)

__device__ __forceinline__ void cp_async16(void* smem, const void* gmem) {
    unsigned saddr = (unsigned)__cvta_generic_to_shared(smem);
    asm volatile("cp.async.cg.shared.global [%0], [%1], 16;\n" :: "r"(saddr), "l"(gmem));
}
__device__ __forceinline__ void cp_commit() {
    asm volatile("cp.async.commit_group;\n" ::: "memory");
}
template <int N>
__device__ __forceinline__ void cp_wait() {
    asm volatile("cp.async.wait_group %0;\n" :: "n"(N) : "memory");
}

// ============================================================
// K1: split-K partial of v[b,h] = dot(w_score[h,:], h_t[b,:]).
// Grid (64 h-chunks, 8 k-chunks) = 512 blocks. One-shot tiles, 1 barrier.
// ============================================================
__global__ void __launch_bounds__(256) k_v(const float* __restrict__ hidden,
                                           const float* __restrict__ wsc) {
    __shared__ float sht[32][132];   // 32 b x 128 k (+4 pad)
    __shared__ float swt[16][132];   // 16 h x 128 k (+4 pad)
    const int t = threadIdx.x;              // 256 threads
    const int h0 = blockIdx.x * 16;         // 64 h-chunks
    const int kb4 = blockIdx.y * 32;        // k-chunk base in float4 units (128 floats)

    const float4* __restrict__ hid4 = reinterpret_cast<const float4*>(hidden);
    const float4* __restrict__ wsc4 = reinterpret_cast<const float4*>(wsc);

    #pragma unroll
    for (int i = 0; i < 4; i++) {
        int fi = t + i * 256;
        int b = fi >> 5, k4 = fi & 31;
        float4 v = hid4[((size_t)b * SS + (SS - 1)) * H4 + kb4 + k4];
        *reinterpret_cast<float4*>(&sht[b][k4 * 4]) = v;
    }
    #pragma unroll
    for (int i = 0; i < 2; i++) {
        int fi = t + i * 256;
        int h = fi >> 5, k4 = fi & 31;
        float4 v = wsc4[(size_t)(h0 + h) * H4 + kb4 + k4];
        *reinterpret_cast<float4*>(&swt[h][k4 * 4]) = v;
    }
    __syncthreads();

    #pragma unroll
    for (int j = 0; j < 2; j++) {
        int o = t + j * 256;
        int b = o >> 4, h = o & 15;
        float a = 0.f;
        #pragma unroll 8
        for (int k = 0; k < 128; k++) a += swt[h][k] * sht[b][k];
        g_vp[((size_t)blockIdx.y * BB + b) * HH + h0 + h] = a;
    }
}

// ============================================================
// K2: big-tile flash attention. 8-row (32 KB) tiles, depth-3 ring in
// 96 KB dynamic smem, 2 barriers per tile, loads for ti+2 issued before
// compute of ti. Warp w scores row w with v held fully in registers.
// ============================================================
__global__ void __launch_bounds__(256) k_attn(const float* __restrict__ hidden) {
    extern __shared__ float4 sbuf[];              // [DEPTH][TILE*H4]
    __shared__ float spart[TILE];                 // per-row scores

    const int b = blockIdx.y;
    const int c = blockIdx.x;
    const int t = threadIdx.x;     // 256
    const int w = t >> 5;          // warp = row within tile
    const int l = t & 31;
    const int s0 = c * RPC;

    const float4* __restrict__ hid = reinterpret_cast<const float4*>(hidden) + (size_t)b * SS * H4;
    const float4* __restrict__ vp4 = reinterpret_cast<const float4*>(g_vp);

    // full v[b] per scoring warp: 8 float4/lane, summed over KC partials
    float4 vv[8];
    #pragma unroll
    for (int k = 0; k < 8; k++) vv[k] = make_float4(0.f, 0.f, 0.f, 0.f);
    #pragma unroll
    for (int p = 0; p < KC; p++) {
        #pragma unroll
        for (int k = 0; k < 8; k++) {
            const float4 a = vp4[((size_t)p * BB + b) * H4 + k * 32 + l];
            vv[k].x += a.x; vv[k].y += a.y; vv[k].z += a.z; vv[k].w += a.w;
        }
    }

    // preload tiles 0,1 (one commit group per tile)
    #pragma unroll
    for (int pre = 0; pre < 2; pre++) {
        #pragma unroll
        for (int j = 0; j < TILE; j++)
            cp_async16(&sbuf[(size_t)pre * (TILE * H4) + j * H4 + t],
                       &hid[(size_t)(s0 + pre * TILE + j) * H4 + t]);
        cp_commit();
    }

    float4 acc = make_float4(0.f, 0.f, 0.f, 0.f);
    float m = -INFINITY, L = 0.f;

    for (int ti = 0; ti < NT; ti++) {
        const float4* tb = &sbuf[(size_t)(ti % DEPTH) * (TILE * H4)];

        cp_wait<1>();
        __syncthreads();     // (A) tile ti resident; accum of ti-1 done by all

        // issue loads for tile ti+2 into slot (ti+2)%DEPTH (= slot of ti-1, free)
        if (ti + 2 < NT) {
            float4* nb = &sbuf[(size_t)((ti + 2) % DEPTH) * (TILE * H4)];
            #pragma unroll
            for (int j = 0; j < TILE; j++)
                cp_async16(&nb[j * H4 + t], &hid[(size_t)(s0 + (ti + 2) * TILE + j) * H4 + t]);
        }
        cp_commit();          // always commit: one group per iteration

        // score: warp w computes full dot of row w with v
        {
            float p = 0.f;
            #pragma unroll
            for (int k = 0; k < 8; k++) {
                const float4 hv = tb[w * H4 + k * 32 + l];
                p += hv.x * vv[k].x + hv.y * vv[k].y + hv.z * vv[k].z + hv.w * vv[k].w;
            }
            #pragma unroll
            for (int o = 16; o > 0; o >>= 1) p += __shfl_xor_sync(0xffffffffu, p, o);
            if (l == 0) spart[w] = p;
        }
        __syncthreads();     // (B) scores visible

        // block-uniform online softmax + accumulate; thread t owns H-slot t
        {
            float s[TILE];
            float mn = m;
            #pragma unroll
            for (int j = 0; j < TILE; j++) { s[j] = spart[j]; mn = fmaxf(mn, s[j]); }
            const float sc = __expf(m - mn);   // 0 on first tile
            float pp[TILE], lsum = 0.f;
            #pragma unroll
            for (int j = 0; j < TILE; j++) { pp[j] = __expf(s[j] - mn); lsum += pp[j]; }

            acc.x *= sc; acc.y *= sc; acc.z *= sc; acc.w *= sc;
            #pragma unroll
            for (int j = 0; j < TILE; j++) {
                const float4 hv = tb[j * H4 + t];
                acc.x += pp[j] * hv.x;
                acc.y += pp[j] * hv.y;
                acc.z += pp[j] * hv.z;
                acc.w += pp[j] * hv.w;
            }
            L = L * sc + lsum;
            m = mn;
        }
    }

    if (t == 0) { g_pm[b * CH + c] = m; g_pl[b * CH + c] = L; }
    reinterpret_cast<float4*>(g_pacc)[((size_t)b * CH + c) * H4 + t] = acc;
}

// ============================================================
// K3: merge 32 chunk partials -> context; build pre = [context ; h_t].
// Grid (B, 4) x 256: group cg sums 8 chunks; smem reduce over cg.
// ============================================================
__global__ void __launch_bounds__(256) k_combine(const float* __restrict__ hidden) {
    const int b = blockIdx.x;
    const int t = threadIdx.x;      // 256
    const int cg = t >> 6;          // 0..3
    const int hl = t & 63;
    __shared__ float sm[CH], sl[CH], wgt[CH];
    __shared__ float sinv;
    __shared__ float4 red[4][64];

    if (t < CH) { sm[t] = g_pm[b * CH + t]; sl[t] = g_pl[b * CH + t]; }
    __syncthreads();

    if (t < 32) {
        float M = sm[t];
        #pragma unroll
        for (int o = 16; o > 0; o >>= 1) M = fmaxf(M, __shfl_xor_sync(0xffffffffu, M, o));
        const float e = __expf(sm[t] - M);
        wgt[t] = e;
        float Lp = sl[t] * e;
        #pragma unroll
        for (int o = 16; o > 0; o >>= 1) Lp += __shfl_xor_sync(0xffffffffu, Lp, o);
        if (t == 0) sinv = 1.f / Lp;
    }
    __syncthreads();

    const int hi = blockIdx.y * 64 + hl;   // float4 index within H4
    const float4* pacc4 = reinterpret_cast<const float4*>(g_pacc);

    float4 ctx = make_float4(0.f, 0.f, 0.f, 0.f);
    #pragma unroll
    for (int cc = 0; cc < 8; cc++) {
        const int c = cg * 8 + cc;
        const float e = wgt[c];
        const float4 a = pacc4[((size_t)b * CH + c) * H4 + hi];
        ctx.x += e * a.x; ctx.y += e * a.y; ctx.z += e * a.z; ctx.w += e * a.w;
    }
    red[cg][hl] = ctx;
    __syncthreads();

    if (cg == 0) {
        const float inv = sinv;
        float4 s = red[0][hl], a1 = red[1][hl], a2 = red[2][hl], a3 = red[3][hl];
        s.x = (s.x + a1.x + a2.x + a3.x) * inv;
        s.y = (s.y + a1.y + a2.y + a3.y) * inv;
        s.z = (s.z + a1.z + a2.z + a3.z) * inv;
        s.w = (s.w + a1.w + a2.w + a3.w) * inv;
        float4* pre4 = reinterpret_cast<float4*>(g_pre);
        pre4[b * (2 * H4) + hi] = s;
        pre4[b * (2 * H4) + H4 + hi] =
            reinterpret_cast<const float4*>(hidden)[((size_t)b * SS + (SS - 1)) * H4 + hi];
    }
}

// ============================================================
// K4: split-K output GEMM, (64 j-chunks x 4 batch-groups) x 256 threads.
// Thread (brel 0..7, u4 0..31): float4 of U for batch b0+brel; 32-deep
// independent LDG.128 loop over j; wout row broadcast across 8 brel groups.
// ============================================================
__global__ void __launch_bounds__(256) k_outp(const float* __restrict__ wout) {
    const int p = blockIdx.x;     // 64
    const int bg = blockIdx.y;    // 4
    const int t = threadIdx.x;    // 256
    const int u4 = t & 31;
    const int brel = t >> 5;      // 0..7
    const int j0 = p * JCW;
    const int b0 = bg * 8;

    __shared__ float spre[8][JCW];   // 1 KB
    spre[t >> 5][t & 31] = g_pre[(b0 + (t >> 5)) * (2 * HH) + j0 + (t & 31)];
    __syncthreads();

    const float4* __restrict__ wo4 = reinterpret_cast<const float4*>(wout);
    float4 acc = make_float4(0.f, 0.f, 0.f, 0.f);
    const float* myp = spre[brel];

    #pragma unroll
    for (int jj = 0; jj < JCW; jj++) {
        const float4 wv = wo4[(size_t)(j0 + jj) * 32 + u4];
        const float pr = myp[jj];
        acc.x += pr * wv.x; acc.y += pr * wv.y; acc.z += pr * wv.z; acc.w += pr * wv.w;
    }
    reinterpret_cast<float4*>(g_pout)[((size_t)p * BB + b0 + brel) * 32 + u4] = acc;
}

// K5: reduce 64 partials (8-way split + smem reduce) + tanh -> output
__global__ void __launch_bounds__(256) k_outf(float* __restrict__ out) {
    const int b = blockIdx.x;   // 32 blocks
    const int t = threadIdx.x;  // 256
    const int u4 = t & 31;
    const int pg = t >> 5;      // 0..7
    __shared__ float4 red[8][32];

    const float4* __restrict__ po4 = reinterpret_cast<const float4*>(g_pout);
    float4 a = make_float4(0.f, 0.f, 0.f, 0.f);
    #pragma unroll
    for (int pp = 0; pp < 8; pp++) {
        const int p = pg * 8 + pp;
        const float4 v = po4[((size_t)p * BB + b) * 32 + u4];
        a.x += v.x; a.y += v.y; a.z += v.z; a.w += v.w;
    }
    red[pg][u4] = a;
    __syncthreads();

    if (pg == 0) {
        float4 s = red[0][u4];
        #pragma unroll
        for (int g = 1; g < 8; g++) {
            const float4 v = red[g][u4];
            s.x += v.x; s.y += v.y; s.z += v.z; s.w += v.w;
        }
        s.x = tanhf(s.x); s.y = tanhf(s.y); s.z = tanhf(s.z); s.w = tanhf(s.w);
        reinterpret_cast<float4*>(out)[b * 32 + u4] = s;
    }
}

extern "C" void kernel_launch(void* const* d_in, const int* in_sizes, int n_in,
                              void* d_out, int out_size) {
    const float* hidden = (const float*)d_in[0];  // (32, 2048, 1024) f32
    const float* wsc    = (const float*)d_in[1];  // (1024, 1024) f32
    const float* wout   = (const float*)d_in[2];  // (2048, 128) f32
    float* out = (float*)d_out;                   // (32, 128) f32

    const int attn_smem = DEPTH * TILE * H4 * (int)sizeof(float4);  // 96 KB
    cudaFuncSetAttribute(k_attn, cudaFuncAttributeMaxDynamicSharedMemorySize, attn_smem);

    k_v<<<dim3(64, KC), 256>>>(hidden, wsc);
    k_attn<<<dim3(CH, BB), 256, attn_smem>>>(hidden);
    k_combine<<<dim3(BB, 4), 256>>>(hidden);
    k_outp<<<dim3(JC2, BG), 256>>>(wout);
    k_outf<<<BB, 256>>>(out);
}